// round 15
// baseline (speedup 1.0000x reference)
#include <cuda_runtime.h>
#include <cstdint>

#define BB   16
#define XS_  256
#define NN   500000
#define LATD 8
#define NKX  129   // XS/2 + 1
#define SROW 257   // padded FFT row stride (floats)

// ---- static scratch (no allocs allowed) ----
__device__ float  g_img [BB * XS_ * XS_];
__device__ float2 g_fc  [BB * NKX * XS_];   // kx-major: [(b*NKX+kx)*XS_ + y]
__device__ float  g_ctfT[BB * NKX * XS_];   // transposed ctf, same layout
__device__ float  g_h   [BB * LATD];
__device__ float  g_pose[BB * 8];

// ============================================================
// 0) pose/MLP prep (1 block, 16 threads; image zero now via memset)
// ============================================================
__global__ void k_prep(const float* __restrict__ rows,
                       const float* __restrict__ shifts,
                       const float* __restrict__ latent,
                       const float* __restrict__ W0, const float* __restrict__ b0,
                       const float* __restrict__ W1, const float* __restrict__ b1,
                       const float* __restrict__ W2, const float* __restrict__ b2,
                       const float* __restrict__ W3, const float* __restrict__ b3) {
    int b = threadIdx.x;
    if (b >= BB) return;
    float rot = rows[b*3+0], tilt = rows[b*3+1], psi = rows[b*3+2];
    float ca = cosf(rot),  sa = sinf(rot);
    float cb = cosf(tilt), sb = sinf(tilt);
    float cg = cosf(psi),  sg = sinf(psi);

    float cgcb  = __fmul_rn(cg, cb);
    float nsgcb = __fmul_rn(-sg, cb);

    float r00 = __fsub_rn(__fmul_rn(cgcb, ca), __fmul_rn(sg, sa));
    float r01 = __fadd_rn(__fmul_rn(cgcb, sa), __fmul_rn(sg, ca));
    float r02 = -__fmul_rn(cg, sb);
    float r10 = __fsub_rn(__fmul_rn(nsgcb, ca), __fmul_rn(cg, sa));
    float r11 = __fadd_rn(__fmul_rn(nsgcb, sa), __fmul_rn(cg, ca));
    float r12 = __fmul_rn(sg, sb);

    g_pose[b*8+0] = r00;
    g_pose[b*8+1] = r01;
    g_pose[b*8+2] = r02;
    g_pose[b*8+3] = r10;
    g_pose[b*8+4] = r11;
    g_pose[b*8+5] = r12;
    g_pose[b*8+6] = shifts[b*2+0];
    g_pose[b*8+7] = shifts[b*2+1];

    float lat[LATD];
    #pragma unroll
    for (int ii = 0; ii < LATD; ii++) lat[ii] = latent[b*LATD+ii];

    float h[LATD], z[LATD];
    #pragma unroll
    for (int j = 0; j < LATD; j++) {
        float acc = 0.0f;
        #pragma unroll
        for (int ii = 0; ii < LATD; ii++) acc = fmaf(lat[ii], W0[ii*LATD+j], acc);
        acc = __fadd_rn(acc, b0[j]);
        h[j] = sinf(__fmul_rn(30.0f, acc));
    }
    const float* Ws[3] = {W1, W2, W3};
    const float* bs[3] = {b1, b2, b3};
    for (int L = 0; L < 3; L++) {
        #pragma unroll
        for (int j = 0; j < LATD; j++) {
            float acc = 0.0f;
            #pragma unroll
            for (int ii = 0; ii < LATD; ii++) acc = fmaf(h[ii], Ws[L][ii*LATD+j], acc);
            acc = __fadd_rn(acc, bs[L][j]);
            z[j] = sinf(acc);
        }
        #pragma unroll
        for (int j = 0; j < LATD; j++) h[j] = __fadd_rn(h[j], z[j]);
    }
    #pragma unroll
    for (int j = 0; j < LATD; j++) g_h[b*LATD+j] = h[j];
}

// ============================================================
// 0b) transpose CTF: ctf[b][y][kx] -> g_ctfT[(b*NKX+kx)*XS_ + y]
// ============================================================
__global__ void k_ctfT(const float* __restrict__ ctf) {
    __shared__ float tile[32][33];
    int b   = blockIdx.z;
    int kx0 = blockIdx.x * 32;
    int y0  = blockIdx.y * 32;
    int tx  = threadIdx.x, ty = threadIdx.y;
    #pragma unroll
    for (int yy = ty; yy < 32; yy += 8) {
        int kx = kx0 + tx;
        tile[yy][tx] = (kx < NKX) ? ctf[(b*XS_ + y0 + yy)*NKX + kx] : 0.0f;
    }
    __syncthreads();
    #pragma unroll
    for (int a = ty; a < 32; a += 8) {
        int kx = kx0 + a;
        if (kx < NKX) g_ctfT[(b*NKX + kx)*XS_ + y0 + tx] = tile[tx][a];
    }
}

// ============================================================
// 1) rotation + decode + scatter-add (bit-identical arithmetic)
// ============================================================
__global__ void __launch_bounds__(256)
k_scatter(const float* __restrict__ coords,
          const float* __restrict__ values,
          const float* __restrict__ Wd,
          const float* __restrict__ bd) {
    __shared__ float4 sh[BB * 2];
    __shared__ float4 sp[BB * 2];
    int t = threadIdx.x;
    if (t < BB * 2) {
        const float4* gh = (const float4*)g_h;
        const float4* gp = (const float4*)g_pose;
        sh[t] = gh[t];
        sp[t] = gp[t];
    }
    __syncthreads();

    int n = blockIdx.x * blockDim.x + t;
    if (n >= NN) return;

    float x  = coords[3*n+0];
    float y  = coords[3*n+1];
    float zc = coords[3*n+2];
    float w[LATD];
    #pragma unroll
    for (int l = 0; l < LATD; l++) w[l] = Wd[l*NN + n];
    float vn  = values[n];
    float bdn = bd[n];

    #pragma unroll
    for (int b = 0; b < BB; b++) {
        float4 pa = sp[b*2+0];
        float4 pb = sp[b*2+1];
        float dx = fmaf(pa.x, x, 0.0f);
        dx = fmaf(pa.y, y,  dx);
        dx = fmaf(pa.z, zc, dx);
        float dy = fmaf(pa.w, x, 0.0f);
        dy = fmaf(pb.x, y,  dy);
        dy = fmaf(pb.y, zc, dy);
        float pxf = rintf(__fadd_rn(__fadd_rn(dx, pb.z), 128.0f));
        float pyf = rintf(__fadd_rn(__fadd_rn(dy, pb.w), 128.0f));
        pxf = fminf(fmaxf(pxf, 0.0f), 255.0f);
        pyf = fminf(fmaxf(pyf, 0.0f), 255.0f);
        int px = (int)pxf;
        int py = (int)pyf;

        float4 h0 = sh[b*2+0];
        float4 h1 = sh[b*2+1];
        float acc = 0.0f;
        acc = fmaf(h0.x, w[0], acc);
        acc = fmaf(h0.y, w[1], acc);
        acc = fmaf(h0.z, w[2], acc);
        acc = fmaf(h0.w, w[3], acc);
        acc = fmaf(h1.x, w[4], acc);
        acc = fmaf(h1.y, w[5], acc);
        acc = fmaf(h1.z, w[6], acc);
        acc = fmaf(h1.w, w[7], acc);
        float v = __fadd_rn(vn, __fadd_rn(acc, bdn));
        atomicAdd(&g_img[(b << 16) + (py << 8) + px], v);
    }
}

// ============================================================
// helpers
// ============================================================
__device__ __forceinline__ float gwt(int d) {
    const float w0 = 0.00443305f;   // |d|=3
    const float w1 = 0.05400558f;   // |d|=2
    const float w2 = 0.24203623f;   // |d|=1
    const float w3 = 0.39905033f;   // d=0
    int a = d < 0 ? -d : d;
    return a == 0 ? w3 : (a == 1 ? w2 : (a == 2 ? w1 : w0));
}

__device__ __forceinline__ int brev8(int i) { return (int)(__brev((unsigned)i) >> 24); }

__device__ __forceinline__ void init_tw(float2* tw, int t) {
    float s, c;
    sincospif((float)t * (1.0f / 128.0f), &s, &c);
    tw[t] = make_float2(c, -s);   // e^{-2pi i t/256}
}

// batched 8-row FFT; 256 threads = (j 0..127) x (rh 0..1), 4 rows each.
// Butterfly math identical to single-row version.
__device__ __forceinline__ void fft256_b8(float* sre, float* sim,
                                          const float2* tw, int t, bool inv) {
    int j  = t & 127;
    int rh = t >> 7;            // rows rh*4 .. rh*4+3
    #pragma unroll
    for (int s = 1; s <= 8; s++) {
        int half = 1 << (s - 1);
        int grp = j >> (s - 1);
        int jj  = j & (half - 1);
        int i0  = grp * (half << 1) + jj;
        int i1  = i0 + half;
        float2 w = tw[jj << (8 - s)];
        float wr = w.x;
        float wi = inv ? -w.y : w.y;
        #pragma unroll
        for (int k = 0; k < 4; k++) {
            int r = rh * 4 + k;
            float xr = sre[r*SROW + i1], xi = sim[r*SROW + i1];
            float vr = xr*wr - xi*wi;
            float vi = xr*wi + xi*wr;
            float ur = sre[r*SROW + i0], ui = sim[r*SROW + i0];
            sre[r*SROW + i0] = ur + vr;  sim[r*SROW + i0] = ui + vi;
            sre[r*SROW + i1] = ur - vr;  sim[r*SROW + i1] = ui - vi;
        }
        __syncthreads();
    }
}

// ============================================================
// 2) fused blur_v + blur_h + row rfft, 8 rows per block.
//    grid = BB*32 = 512, block = 256. Coalesced global accesses.
// ============================================================
__global__ void __launch_bounds__(256) k_blur_rfft() {
    __shared__ float poolA[14 * 256];        // raw rows; later aliased as sre (8*SROW=2056)
    __shared__ float poolB[8 * SROW];        // bv (8*256 used); later aliased as sim
    __shared__ float2 tw[128];
    float* raw = poolA;
    float* sre = poolA;
    float* bv  = poolB;
    float* sim = poolB;

    int t = threadIdx.x;
    if (t < 128) init_tw(tw, t);
    int blk = blockIdx.x;
    int b  = blk >> 5;
    int y0 = (blk & 31) << 3;

    // load rows y0-3 .. y0+10 (zero outside)
    #pragma unroll
    for (int rr = 0; rr < 14; rr++) {
        int y = y0 + rr - 3;
        raw[rr * 256 + t] = (y >= 0 && y < XS_)
            ? g_img[(((b << 8) + y) << 8) + t] : 0.0f;
    }
    __syncthreads();

    // vertical blur (w*0 out-of-range == skip)
    float vv[8];
    #pragma unroll
    for (int r = 0; r < 8; r++) {
        float acc = 0.0f;
        #pragma unroll
        for (int d = -3; d <= 3; d++)
            acc += gwt(d) * raw[(r + 3 + d) * 256 + t];
        vv[r] = acc;
    }
    __syncthreads();          // all raw reads done (poolA will become sre)
    #pragma unroll
    for (int r = 0; r < 8; r++) bv[r * 256 + t] = vv[r];
    __syncthreads();

    // horizontal blur -> FFT input at bit-reversed positions
    int p = brev8(t);
    #pragma unroll
    for (int r = 0; r < 8; r++) {
        float acc = 0.0f;
        #pragma unroll
        for (int d = -3; d <= 3; d++) {
            int xx = t + d;
            if (xx >= 0 && xx < XS_)
                acc += gwt(d) * bv[r * 256 + xx];
        }
        sre[r * SROW + p] = acc;
    }
    __syncthreads();          // all bv reads done (poolB will become sim)
    #pragma unroll
    for (int r = 0; r < 8; r++) sim[r * SROW + t] = 0.0f;
    __syncthreads();

    fft256_b8(sre, sim, tw, t, false);

    // write kx-major, coalesced: 8 consecutive y per kx
    int yl  = t & 7;
    int kxi = t >> 3;          // 0..31
    float2* dst = &g_fc[(b * NKX) * XS_ + y0 + yl];
    #pragma unroll
    for (int c = 0; c < 4; c++) {
        int kx = c * 32 + kxi;
        dst[kx * XS_] = make_float2(sre[yl * SROW + kx], sim[yl * SROW + kx]);
    }
    if (t < 8) {
        float2* d2 = &g_fc[(b * NKX + 128) * XS_ + y0 + t];
        *d2 = make_float2(sre[t * SROW + 128], sim[t * SROW + 128]);
    }
}

// ============================================================
// 3) column FFT over y + CTF + inverse column FFT; block per (b,kx).
// ============================================================
__device__ __forceinline__ void fft256_tw(float* sre, float* sim,
                                          const float2* tw, int t, bool inv) {
    #pragma unroll
    for (int s = 1; s <= 8; s++) {
        int half = 1 << (s - 1);
        int len  = half << 1;
        int grp = t >> (s - 1);
        int j   = t & (half - 1);
        int i0  = grp * len + j;
        int i1  = i0 + half;
        float2 w = tw[j << (8 - s)];
        float wr = w.x;
        float wi = inv ? -w.y : w.y;
        float xr = sre[i1], xi = sim[i1];
        float vr = xr*wr - xi*wi;
        float vi = xr*wi + xi*wr;
        float ur = sre[i0], ui = sim[i0];
        sre[i0] = ur + vr;  sim[i0] = ui + vi;
        sre[i1] = ur - vr;  sim[i1] = ui - vi;
        __syncthreads();
    }
}

__global__ void __launch_bounds__(128) k_col_ctf() {
    __shared__ float sre[256], sim[256];
    __shared__ float2 tw[128];
    int t = threadIdx.x;
    init_tw(tw, t);
    int col = blockIdx.x;                 // b*NKX + kx
    float2* fc = &g_fc[col * XS_];
    const float* ct = &g_ctfT[col * XS_];

    float2 a0 = fc[t];
    float2 a1 = fc[t + 128];
    int r0 = brev8(t), r1 = brev8(t + 128);
    sre[r0] = a0.x;  sim[r0] = a0.y;
    sre[r1] = a1.x;  sim[r1] = a1.y;
    __syncthreads();
    fft256_tw(sre, sim, tw, t, false);

    float c0 = ct[t];
    float c1 = ct[t + 128];
    float ar = sre[t]       * c0, ai = sim[t]       * c0;
    float br = sre[t + 128] * c1, bi = sim[t + 128] * c1;
    __syncthreads();
    sre[r0] = ar;  sim[r0] = ai;
    sre[r1] = br;  sim[r1] = bi;
    __syncthreads();
    fft256_tw(sre, sim, tw, t, true);     // unscaled inverse

    fc[t]       = make_float2(sre[t],       sim[t]);
    fc[t + 128] = make_float2(sre[t + 128], sim[t + 128]);
}

// ============================================================
// 4) batched row irfft (Hermitian), 8 rows per block -> d_out.
// ============================================================
__global__ void __launch_bounds__(256) k_irfft_b8(float* __restrict__ out) {
    __shared__ float sre[8 * SROW], sim[8 * SROW];
    __shared__ float2 tw[128];
    int t = threadIdx.x;
    if (t < 128) init_tw(tw, t);
    int blk = blockIdx.x;
    int b  = blk >> 5;
    int y0 = (blk & 31) << 3;

    int yl  = t & 7;
    int kxi = t >> 3;          // 0..31
    const float2* src = &g_fc[(b * NKX) * XS_ + y0 + yl];
    #pragma unroll
    for (int c = 0; c < 4; c++) {
        int kx = c * 32 + kxi;
        float2 v = src[kx * XS_];
        int p1 = brev8(kx);
        sre[yl * SROW + p1] = v.x;
        sim[yl * SROW + p1] = v.y;
        if (kx >= 1) {
            int p2 = brev8(256 - kx);
            sre[yl * SROW + p2] = v.x;
            sim[yl * SROW + p2] = -v.y;
        }
    }
    if (t < 8) {
        float2 v = g_fc[(b * NKX + 128) * XS_ + y0 + t];
        int p1 = brev8(128);
        sre[t * SROW + p1] = v.x;
        sim[t * SROW + p1] = v.y;
    }
    __syncthreads();

    fft256_b8(sre, sim, tw, t, true);

    const float s = 1.0f / 65536.0f;
    #pragma unroll
    for (int r = 0; r < 8; r++)
        out[(((b << 8) + y0 + r) << 8) + t] = sre[r * SROW + t] * s;
}

// ============================================================
extern "C" void kernel_launch(void* const* d_in, const int* in_sizes, int n_in,
                              void* d_out, int out_size) {
    const float* rows   = (const float*)d_in[0];
    const float* shifts = (const float*)d_in[1];
    const float* latent = (const float*)d_in[2];
    const float* coords = (const float*)d_in[3];
    const float* values = (const float*)d_in[4];
    const float* W0     = (const float*)d_in[5];
    const float* b0     = (const float*)d_in[6];
    const float* W1     = (const float*)d_in[7];
    const float* b1     = (const float*)d_in[8];
    const float* W2     = (const float*)d_in[9];
    const float* b2     = (const float*)d_in[10];
    const float* W3     = (const float*)d_in[11];
    const float* b3     = (const float*)d_in[12];
    const float* Wd     = (const float*)d_in[13];
    const float* bd     = (const float*)d_in[14];
    const float* ctf    = (const float*)d_in[15];
    float* out = (float*)d_out;

    void* imgPtr = nullptr;
    cudaGetSymbolAddress(&imgPtr, g_img);
    cudaMemsetAsync(imgPtr, 0, BB * XS_ * XS_ * sizeof(float));

    k_prep<<<1, 16>>>(rows, shifts, latent, W0, b0, W1, b1, W2, b2, W3, b3);
    {
        dim3 g(5, 8, BB), blk(32, 8);
        k_ctfT<<<g, blk>>>(ctf);
    }
    k_scatter<<<(NN + 255) / 256, 256>>>(coords, values, Wd, bd);
    k_blur_rfft<<<BB * 32, 256>>>();
    k_col_ctf<<<BB * NKX, 128>>>();
    k_irfft_b8<<<BB * 32, 256>>>(out);
}

// round 17
// speedup vs baseline: 1.0319x; 1.0319x over previous
#include <cuda_runtime.h>
#include <cstdint>

#define BB   16
#define XS_  256
#define NN   500000
#define LATD 8
#define NKX  129   // XS/2 + 1
#define SRC  257   // float2 row stride in 16-row workspaces

// ---- static scratch (no allocs allowed) ----
__device__ float  g_img [BB * XS_ * XS_];
__device__ float2 g_fc  [BB * NKX * XS_];   // kx-major: [(b*NKX+kx)*XS_ + y]
__device__ float  g_ctfT[BB * NKX * XS_];   // transposed ctf, same layout
__device__ float  g_h   [BB * LATD];
__device__ float  g_pose[BB * 8];

// ============================================================
// 0) pose/MLP prep (1 block, 16 threads; image zero via memset)
// ============================================================
__global__ void k_prep(const float* __restrict__ rows,
                       const float* __restrict__ shifts,
                       const float* __restrict__ latent,
                       const float* __restrict__ W0, const float* __restrict__ b0,
                       const float* __restrict__ W1, const float* __restrict__ b1,
                       const float* __restrict__ W2, const float* __restrict__ b2,
                       const float* __restrict__ W3, const float* __restrict__ b3) {
    int b = threadIdx.x;
    if (b >= BB) return;
    float rot = rows[b*3+0], tilt = rows[b*3+1], psi = rows[b*3+2];
    float ca = cosf(rot),  sa = sinf(rot);
    float cb = cosf(tilt), sb = sinf(tilt);
    float cg = cosf(psi),  sg = sinf(psi);

    float cgcb  = __fmul_rn(cg, cb);
    float nsgcb = __fmul_rn(-sg, cb);

    float r00 = __fsub_rn(__fmul_rn(cgcb, ca), __fmul_rn(sg, sa));
    float r01 = __fadd_rn(__fmul_rn(cgcb, sa), __fmul_rn(sg, ca));
    float r02 = -__fmul_rn(cg, sb);
    float r10 = __fsub_rn(__fmul_rn(nsgcb, ca), __fmul_rn(cg, sa));
    float r11 = __fadd_rn(__fmul_rn(nsgcb, sa), __fmul_rn(cg, ca));
    float r12 = __fmul_rn(sg, sb);

    g_pose[b*8+0] = r00;
    g_pose[b*8+1] = r01;
    g_pose[b*8+2] = r02;
    g_pose[b*8+3] = r10;
    g_pose[b*8+4] = r11;
    g_pose[b*8+5] = r12;
    g_pose[b*8+6] = shifts[b*2+0];
    g_pose[b*8+7] = shifts[b*2+1];

    float lat[LATD];
    #pragma unroll
    for (int ii = 0; ii < LATD; ii++) lat[ii] = latent[b*LATD+ii];

    float h[LATD], z[LATD];
    #pragma unroll
    for (int j = 0; j < LATD; j++) {
        float acc = 0.0f;
        #pragma unroll
        for (int ii = 0; ii < LATD; ii++) acc = fmaf(lat[ii], W0[ii*LATD+j], acc);
        acc = __fadd_rn(acc, b0[j]);
        h[j] = sinf(__fmul_rn(30.0f, acc));
    }
    const float* Ws[3] = {W1, W2, W3};
    const float* bs[3] = {b1, b2, b3};
    for (int L = 0; L < 3; L++) {
        #pragma unroll
        for (int j = 0; j < LATD; j++) {
            float acc = 0.0f;
            #pragma unroll
            for (int ii = 0; ii < LATD; ii++) acc = fmaf(h[ii], Ws[L][ii*LATD+j], acc);
            acc = __fadd_rn(acc, bs[L][j]);
            z[j] = sinf(acc);
        }
        #pragma unroll
        for (int j = 0; j < LATD; j++) h[j] = __fadd_rn(h[j], z[j]);
    }
    #pragma unroll
    for (int j = 0; j < LATD; j++) g_h[b*LATD+j] = h[j];
}

// ============================================================
// 0b) transpose CTF: ctf[b][y][kx] -> g_ctfT[(b*NKX+kx)*XS_ + y]
// ============================================================
__global__ void k_ctfT(const float* __restrict__ ctf) {
    __shared__ float tile[32][33];
    int b   = blockIdx.z;
    int kx0 = blockIdx.x * 32;
    int y0  = blockIdx.y * 32;
    int tx  = threadIdx.x, ty = threadIdx.y;
    #pragma unroll
    for (int yy = ty; yy < 32; yy += 8) {
        int kx = kx0 + tx;
        tile[yy][tx] = (kx < NKX) ? ctf[(b*XS_ + y0 + yy)*NKX + kx] : 0.0f;
    }
    __syncthreads();
    #pragma unroll
    for (int a = ty; a < 32; a += 8) {
        int kx = kx0 + a;
        if (kx < NKX) g_ctfT[(b*NKX + kx)*XS_ + y0 + tx] = tile[tx][a];
    }
}

// ============================================================
// 1) rotation + decode + scatter-add (bit-identical arithmetic)
// ============================================================
__global__ void __launch_bounds__(256)
k_scatter(const float* __restrict__ coords,
          const float* __restrict__ values,
          const float* __restrict__ Wd,
          const float* __restrict__ bd) {
    __shared__ float4 sh[BB * 2];
    __shared__ float4 sp[BB * 2];
    int t = threadIdx.x;
    if (t < BB * 2) {
        const float4* gh = (const float4*)g_h;
        const float4* gp = (const float4*)g_pose;
        sh[t] = gh[t];
        sp[t] = gp[t];
    }
    __syncthreads();

    int n = blockIdx.x * blockDim.x + t;
    if (n >= NN) return;

    float x  = coords[3*n+0];
    float y  = coords[3*n+1];
    float zc = coords[3*n+2];
    float w[LATD];
    #pragma unroll
    for (int l = 0; l < LATD; l++) w[l] = Wd[l*NN + n];
    float vn  = values[n];
    float bdn = bd[n];

    #pragma unroll
    for (int b = 0; b < BB; b++) {
        float4 pa = sp[b*2+0];
        float4 pb = sp[b*2+1];
        float dx = fmaf(pa.x, x, 0.0f);
        dx = fmaf(pa.y, y,  dx);
        dx = fmaf(pa.z, zc, dx);
        float dy = fmaf(pa.w, x, 0.0f);
        dy = fmaf(pb.x, y,  dy);
        dy = fmaf(pb.y, zc, dy);
        float pxf = rintf(__fadd_rn(__fadd_rn(dx, pb.z), 128.0f));
        float pyf = rintf(__fadd_rn(__fadd_rn(dy, pb.w), 128.0f));
        pxf = fminf(fmaxf(pxf, 0.0f), 255.0f);
        pyf = fminf(fmaxf(pyf, 0.0f), 255.0f);
        int px = (int)pxf;
        int py = (int)pyf;

        float4 h0 = sh[b*2+0];
        float4 h1 = sh[b*2+1];
        float acc = 0.0f;
        acc = fmaf(h0.x, w[0], acc);
        acc = fmaf(h0.y, w[1], acc);
        acc = fmaf(h0.z, w[2], acc);
        acc = fmaf(h0.w, w[3], acc);
        acc = fmaf(h1.x, w[4], acc);
        acc = fmaf(h1.y, w[5], acc);
        acc = fmaf(h1.z, w[6], acc);
        acc = fmaf(h1.w, w[7], acc);
        float v = __fadd_rn(vn, __fadd_rn(acc, bdn));
        atomicAdd(&g_img[(b << 16) + (py << 8) + px], v);
    }
}

// ============================================================
// helpers — radix-4 256-pt FFT on float2 complex
// ============================================================
__device__ __forceinline__ float gwt(int d) {
    const float w0 = 0.00443305f;   // |d|=3
    const float w1 = 0.05400558f;   // |d|=2
    const float w2 = 0.24203623f;   // |d|=1
    const float w3 = 0.39905033f;   // d=0
    int a = d < 0 ? -d : d;
    return a == 0 ? w3 : (a == 1 ? w2 : (a == 2 ? w1 : w0));
}

// base-4 digit reversal of 8-bit index
__device__ __forceinline__ int drev4(int i) {
    return ((i & 3) << 6) | ((i & 12) << 2) | ((i & 48) >> 2) | ((i & 192) >> 6);
}

// tw[k] = e^{-2pi i k/256}, k in [0,256)
__device__ __forceinline__ void init_tw256(float2* tw, int t, int nthr) {
    for (int k = t; k < 256; k += nthr) {
        float s, c;
        sincospif((float)k * (1.0f / 128.0f), &s, &c);
        tw[k] = make_float2(c, -s);
    }
}

__device__ __forceinline__ float2 cmulw(float2 w, float2 v, bool inv) {
    float wi = inv ? -w.y : w.y;
    return make_float2(w.x * v.x - wi * v.y, w.x * v.y + wi * v.x);
}

// one radix-4 butterfly (stage s: len=4^s) at butterfly index bf on row p
template<int S>
__device__ __forceinline__ void r4_bfly(float2* p, const float2* tw, int bf, bool inv) {
    const int sh = 2 * (S - 1);
    const int quarter = 1 << sh;
    int g = bf >> sh;
    int j = bf & (quarter - 1);
    int e = j << (8 - 2 * S);
    int i0 = (g << (2 * S)) + j;
    int i1 = i0 + quarter, i2 = i1 + quarter, i3 = i2 + quarter;
    float2 t0 = p[i0];
    float2 t1 = cmulw(tw[e],     p[i1], inv);
    float2 t2 = cmulw(tw[2 * e], p[i2], inv);
    float2 t3 = cmulw(tw[3 * e], p[i3], inv);
    float2 u0 = make_float2(t0.x + t2.x, t0.y + t2.y);
    float2 u1 = make_float2(t0.x - t2.x, t0.y - t2.y);
    float2 u2 = make_float2(t1.x + t3.x, t1.y + t3.y);
    float2 u3 = make_float2(t1.x - t3.x, t1.y - t3.y);
    p[i0] = make_float2(u0.x + u2.x, u0.y + u2.y);
    p[i2] = make_float2(u0.x - u2.x, u0.y - u2.y);
    if (!inv) {
        p[i1] = make_float2(u1.x + u3.y, u1.y - u3.x);   // u1 - i*u3
        p[i3] = make_float2(u1.x - u3.y, u1.y + u3.x);   // u1 + i*u3
    } else {
        p[i1] = make_float2(u1.x - u3.y, u1.y + u3.x);
        p[i3] = make_float2(u1.x + u3.y, u1.y - u3.x);
    }
}

// batched 16-row radix-4 FFT; 256 threads: bf = t&63, row group = t>>6 (4 rows each)
__device__ __forceinline__ void fft256_r4_b16(float2* ws, const float2* tw, int t, bool inv) {
    int bf = t & 63;
    int rg = (t >> 6) * 4;
    #pragma unroll
    for (int k = 0; k < 4; k++) r4_bfly<1>(ws + (rg + k) * SRC, tw, bf, inv);
    __syncthreads();
    #pragma unroll
    for (int k = 0; k < 4; k++) r4_bfly<2>(ws + (rg + k) * SRC, tw, bf, inv);
    __syncthreads();
    #pragma unroll
    for (int k = 0; k < 4; k++) r4_bfly<3>(ws + (rg + k) * SRC, tw, bf, inv);
    __syncthreads();
    #pragma unroll
    for (int k = 0; k < 4; k++) r4_bfly<4>(ws + (rg + k) * SRC, tw, bf, inv);
    __syncthreads();
}

// ============================================================
// 2) fused blur_v + blur_h + row rfft, 16 rows/block, radix-4 float2.
//    grid = BB*16, block = 256.
// ============================================================
__global__ void __launch_bounds__(256) k_blur_rfft() {
    __shared__ float2 ws[16 * SRC];          // 32896 B (aliased as raw staging)
    __shared__ float2 tw[256];
    float* raw = (float*)ws;                 // 22*256 floats = 22528 B
    int t = threadIdx.x;
    init_tw256(tw, t, 256);
    int blk = blockIdx.x;
    int b  = blk >> 4;
    int y0 = (blk & 15) << 4;

    // load rows y0-3 .. y0+18 (zero outside)
    #pragma unroll
    for (int rr = 0; rr < 22; rr++) {
        int y = y0 + rr - 3;
        raw[rr * 256 + t] = (y >= 0 && y < XS_)
            ? g_img[(((b << 8) + y) << 8) + t] : 0.0f;
    }
    __syncthreads();

    // vertical blur into registers
    float acc[16];
    #pragma unroll
    for (int r = 0; r < 16; r++) {
        float a = 0.0f;
        #pragma unroll
        for (int d = -3; d <= 3; d++)
            a += gwt(d) * raw[(r + 3 + d) * 256 + t];
        acc[r] = a;
    }
    __syncthreads();             // raw dead; ws reused
    #pragma unroll
    for (int r = 0; r < 16; r++) ws[r * SRC + t] = make_float2(acc[r], 0.0f);
    __syncthreads();

    // horizontal blur into registers
    #pragma unroll
    for (int r = 0; r < 16; r++) {
        float a = 0.0f;
        #pragma unroll
        for (int d = -3; d <= 3; d++) {
            int xx = t + d;
            if (xx >= 0 && xx < XS_)
                a += gwt(d) * ws[r * SRC + xx].x;
        }
        acc[r] = a;
    }
    __syncthreads();
    int p = drev4(t);
    #pragma unroll
    for (int r = 0; r < 16; r++) ws[r * SRC + p] = make_float2(acc[r], 0.0f);
    __syncthreads();

    fft256_r4_b16(ws, tw, t, false);

    // write kx-major, coalesced: 16 consecutive y per kx
    int yl  = t & 15;
    int kxi = t >> 4;
    float2* dst = &g_fc[(b * NKX) * XS_ + y0 + yl];
    #pragma unroll
    for (int c = 0; c < 8; c++) {
        int kx = c * 16 + kxi;
        dst[kx * XS_] = ws[yl * SRC + kx];
    }
    if (t < 16)
        g_fc[(b * NKX + 128) * XS_ + y0 + t] = ws[t * SRC + 128];
}

// ============================================================
// 3) column FFT + CTF + inverse, 2 columns per 128-thread block.
//    grid = BB*65 (last pair half-valid). All global access contiguous.
// ============================================================
__global__ void __launch_bounds__(128) k_col_ctf() {
    __shared__ float2 ws[2 * SRC];
    __shared__ float2 tw[256];
    int t = threadIdx.x;
    init_tw256(tw, t, 128);
    int blk = blockIdx.x;
    int b  = blk / 65;
    int pp = blk % 65;
    int ci = t >> 6;                 // which of the 2 columns
    int bf = t & 63;
    int kx = pp * 2 + ci;
    bool valid = (kx < NKX);
    float2* w = ws + ci * SRC;
    float2* fc = &g_fc[(b * NKX + (valid ? kx : 0)) * XS_];
    const float* ct = &g_ctfT[(b * NKX + (valid ? kx : 0)) * XS_];

    float2 vals[4];
    #pragma unroll
    for (int q = 0; q < 4; q++) {
        int y = bf + 64 * q;
        vals[q] = valid ? fc[y] : make_float2(0.0f, 0.0f);
    }
    #pragma unroll
    for (int q = 0; q < 4; q++) w[drev4(bf + 64 * q)] = vals[q];
    __syncthreads();

    r4_bfly<1>(w, tw, bf, false); __syncthreads();
    r4_bfly<2>(w, tw, bf, false); __syncthreads();
    r4_bfly<3>(w, tw, bf, false); __syncthreads();
    r4_bfly<4>(w, tw, bf, false); __syncthreads();

    #pragma unroll
    for (int q = 0; q < 4; q++) {
        int y = bf + 64 * q;
        float c = valid ? ct[y] : 0.0f;
        float2 v = w[y];
        vals[q] = make_float2(v.x * c, v.y * c);
    }
    __syncthreads();
    #pragma unroll
    for (int q = 0; q < 4; q++) w[drev4(bf + 64 * q)] = vals[q];
    __syncthreads();

    r4_bfly<1>(w, tw, bf, true); __syncthreads();
    r4_bfly<2>(w, tw, bf, true); __syncthreads();
    r4_bfly<3>(w, tw, bf, true); __syncthreads();
    r4_bfly<4>(w, tw, bf, true); __syncthreads();

    if (valid) {
        #pragma unroll
        for (int q = 0; q < 4; q++) {
            int y = bf + 64 * q;
            fc[y] = w[y];
        }
    }
}

// ============================================================
// 4) batched row irfft (Hermitian), 16 rows/block, radix-4 -> d_out
// ============================================================
__global__ void __launch_bounds__(256) k_irfft_b16(float* __restrict__ out) {
    __shared__ float2 ws[16 * SRC];
    __shared__ float2 tw[256];
    int t = threadIdx.x;
    init_tw256(tw, t, 256);
    int blk = blockIdx.x;
    int b  = blk >> 4;
    int y0 = (blk & 15) << 4;

    int yl  = t & 15;
    int kxi = t >> 4;
    const float2* src = &g_fc[(b * NKX) * XS_ + y0 + yl];
    #pragma unroll
    for (int c = 0; c < 8; c++) {
        int kx = c * 16 + kxi;
        float2 v = src[kx * XS_];
        ws[yl * SRC + drev4(kx)] = v;
        if (kx >= 1)
            ws[yl * SRC + drev4(256 - kx)] = make_float2(v.x, -v.y);
    }
    if (t < 16) {
        float2 v = g_fc[(b * NKX + 128) * XS_ + y0 + t];
        ws[t * SRC + drev4(128)] = v;
    }
    __syncthreads();

    fft256_r4_b16(ws, tw, t, true);

    const float s = 1.0f / 65536.0f;
    #pragma unroll
    for (int r = 0; r < 16; r++)
        out[(((b << 8) + y0 + r) << 8) + t] = ws[r * SRC + t].x * s;
}

// ============================================================
extern "C" void kernel_launch(void* const* d_in, const int* in_sizes, int n_in,
                              void* d_out, int out_size) {
    const float* rows   = (const float*)d_in[0];
    const float* shifts = (const float*)d_in[1];
    const float* latent = (const float*)d_in[2];
    const float* coords = (const float*)d_in[3];
    const float* values = (const float*)d_in[4];
    const float* W0     = (const float*)d_in[5];
    const float* b0     = (const float*)d_in[6];
    const float* W1     = (const float*)d_in[7];
    const float* b1     = (const float*)d_in[8];
    const float* W2     = (const float*)d_in[9];
    const float* b2     = (const float*)d_in[10];
    const float* W3     = (const float*)d_in[11];
    const float* b3     = (const float*)d_in[12];
    const float* Wd     = (const float*)d_in[13];
    const float* bd     = (const float*)d_in[14];
    const float* ctf    = (const float*)d_in[15];
    float* out = (float*)d_out;

    void* imgPtr = nullptr;
    cudaGetSymbolAddress(&imgPtr, g_img);
    cudaMemsetAsync(imgPtr, 0, BB * XS_ * XS_ * sizeof(float));

    k_prep<<<1, 16>>>(rows, shifts, latent, W0, b0, W1, b1, W2, b2, W3, b3);
    {
        dim3 g(5, 8, BB), blk(32, 8);
        k_ctfT<<<g, blk>>>(ctf);
    }
    k_scatter<<<(NN + 255) / 256, 256>>>(coords, values, Wd, bd);
    k_blur_rfft<<<BB * 16, 256>>>();
    k_col_ctf<<<BB * 65, 128>>>();
    k_irfft_b16<<<BB * 16, 256>>>(out);
}